// round 1
// baseline (speedup 1.0000x reference)
#include <cuda_runtime.h>
#include <cstdint>

#define Cc 64
#define CO 64
#define Ss 256
#define LL (Ss * Ss)

// Fused Reverb kernel.
// Math identity: fold(weight * unfold(x))[c,y,x] = x[c,y,x] * Wsum[c,y,x]
// where Wsum[c,y,x] = sum_{i,j in 0..2, boundary-valid} weight[c, i*3+j, (y+1-i)*S + (x+1-j)]
// then out[o,l] = sum_c conv[c*CO+o] * x[c,l] * Wsum[c,l]
__global__ __launch_bounds__(128) void reverb_fused_kernel(
    const float* __restrict__ x,      // (C, L)
    const float* __restrict__ w,      // (C*9, L)
    const float* __restrict__ conv,   // (C, CO)
    float* __restrict__ out)          // (CO, L)
{
    __shared__ float sconv[Cc * CO];  // 16 KB
    const int tid = threadIdx.x;
    for (int i = tid; i < Cc * CO; i += blockDim.x) sconv[i] = conv[i];
    __syncthreads();

    const int l = blockIdx.x * blockDim.x + tid;
    const int y = l >> 8;
    const int xx = l & 255;

    // 64 fp32 accumulators packed as 32 register pairs for f32x2 FMA
    unsigned long long acc[CO / 2];
#pragma unroll
    for (int o = 0; o < CO / 2; o++) acc[o] = 0ull;

    for (int c = 0; c < Cc; c++) {
        // Gather the 9 shifted weight taps with boundary masking
        const float* wc = w + (size_t)c * 9 * LL;
        float wsum = 0.0f;
#pragma unroll
        for (int i = 0; i < 3; i++) {
            const int ry = y + 1 - i;
            if ((unsigned)ry < (unsigned)Ss) {
#pragma unroll
                for (int j = 0; j < 3; j++) {
                    const int rx = xx + 1 - j;
                    if ((unsigned)rx < (unsigned)Ss) {
                        wsum += __ldg(wc + (i * 3 + j) * LL + ry * Ss + rx);
                    }
                }
            }
        }
        const float gval = __ldg(x + c * LL + l) * wsum;

        // broadcast gval into both halves of a 64-bit packed operand
        unsigned long long g2;
        asm("mov.b64 %0, {%1, %1};" : "=l"(g2) : "f"(gval));

        // conv row c, read as packed pairs from shared (broadcast, conflict-free)
        const unsigned long long* cv =
            reinterpret_cast<const unsigned long long*>(sconv + c * CO);
#pragma unroll
        for (int o = 0; o < CO / 2; o++) {
            asm("fma.rn.f32x2 %0, %1, %2, %0;"
                : "+l"(acc[o]) : "l"(g2), "l"(cv[o]));
        }
    }

    // Write out: out[o*L + l], coalesced across threads for each o
#pragma unroll
    for (int o = 0; o < CO / 2; o++) {
        unsigned int lo, hi;
        asm("mov.b64 {%0, %1}, %2;" : "=r"(lo), "=r"(hi) : "l"(acc[o]));
        out[(size_t)(2 * o) * LL + l] = __uint_as_float(lo);
        out[(size_t)(2 * o + 1) * LL + l] = __uint_as_float(hi);
    }
}

extern "C" void kernel_launch(void* const* d_in, const int* in_sizes, int n_in,
                              void* d_out, int out_size) {
    const float* x    = (const float*)d_in[0];  // (1, C, S, S)
    const float* w    = (const float*)d_in[1];  // (1, C*9, L)
    const float* conv = (const float*)d_in[2];  // (C, CO)
    float* out = (float*)d_out;                 // (1, CO, S, S)

    const int threads = 128;
    const int blocks = LL / threads;  // 512
    reverb_fused_kernel<<<blocks, threads>>>(x, w, conv, out);
}

// round 2
// speedup vs baseline: 2.1478x; 2.1478x over previous
#include <cuda_runtime.h>
#include <cstdint>

#define Cc 64
#define CO 64
#define Ss 256
#define LL (Ss * Ss)

// 16 MB scratch for g[c,l] = x[c,l] * Wsum[c,l]
__device__ float g_scratch[Cc * LL];

// ---------------------------------------------------------------------------
// Kernel A: streaming tap-gather.
// g[c,y,x] = x[c,y,x] * sum_{i,j in 0..2, valid} w[c*9 + i*3+j, (y+1-i)*S + (x+1-j)]
// One thread per (c,l) element. All 10 loads independent -> high MLP.
// ---------------------------------------------------------------------------
__global__ __launch_bounds__(256) void reverb_gather_kernel(
    const float* __restrict__ x,   // (C, L)
    const float* __restrict__ w)   // (C*9, L)
{
    const int t = blockIdx.x * 256 + threadIdx.x;   // 0 .. C*L-1
    const int c = t >> 16;
    const int l = t & (LL - 1);
    const int y = l >> 8;
    const int xx = l & 255;

    const float* wc = w + (size_t)c * 9 * LL;

    float wsum = 0.0f;
#pragma unroll
    for (int i = 0; i < 3; i++) {
        const int ry = y + 1 - i;
        const bool vy = (unsigned)ry < (unsigned)Ss;
        const int ryc = vy ? ry : y;                 // clamped (always in-bounds)
#pragma unroll
        for (int j = 0; j < 3; j++) {
            const int rx = xx + 1 - j;
            const bool vx = (unsigned)rx < (unsigned)Ss;
            const int rxc = vx ? rx : xx;
            const float m = (vy && vx) ? 1.0f : 0.0f;
            const float v = __ldg(wc + (i * 3 + j) * LL + ryc * Ss + rxc);
            wsum = fmaf(m, v, wsum);
        }
    }

    g_scratch[t] = __ldg(x + t) * wsum;
}

// ---------------------------------------------------------------------------
// Kernel B: channel mix. out[o,l] = sum_c conv[c,o] * g[c,l]
// One thread per pixel, 64 fp32 accumulators as 32 packed f32x2 pairs.
// ---------------------------------------------------------------------------
__global__ __launch_bounds__(256) void reverb_mix_kernel(
    const float* __restrict__ conv,   // (C, CO)
    float* __restrict__ out)          // (CO, L)
{
    __shared__ float sconv[Cc * CO];  // 16 KB
    const int tid = threadIdx.x;
    for (int i = tid; i < Cc * CO; i += 256) sconv[i] = conv[i];
    __syncthreads();

    const int l = blockIdx.x * 256 + tid;

    unsigned long long acc[CO / 2];
#pragma unroll
    for (int o = 0; o < CO / 2; o++) acc[o] = 0ull;

#pragma unroll 4
    for (int c = 0; c < Cc; c++) {
        const float gval = g_scratch[c * LL + l];
        unsigned long long g2;
        asm("mov.b64 %0, {%1, %1};" : "=l"(g2) : "f"(gval));
        const unsigned long long* cv =
            reinterpret_cast<const unsigned long long*>(sconv + c * CO);
#pragma unroll
        for (int o = 0; o < CO / 2; o++) {
            asm("fma.rn.f32x2 %0, %1, %2, %0;"
                : "+l"(acc[o]) : "l"(g2), "l"(cv[o]));
        }
    }

#pragma unroll
    for (int o = 0; o < CO / 2; o++) {
        unsigned int lo, hi;
        asm("mov.b64 {%0, %1}, %2;" : "=r"(lo), "=r"(hi) : "l"(acc[o]));
        out[(size_t)(2 * o) * LL + l] = __uint_as_float(lo);
        out[(size_t)(2 * o + 1) * LL + l] = __uint_as_float(hi);
    }
}

extern "C" void kernel_launch(void* const* d_in, const int* in_sizes, int n_in,
                              void* d_out, int out_size) {
    const float* x    = (const float*)d_in[0];  // (1, C, S, S)
    const float* w    = (const float*)d_in[1];  // (1, C*9, L)
    const float* conv = (const float*)d_in[2];  // (C, CO)
    float* out = (float*)d_out;                 // (1, CO, S, S)

    reverb_gather_kernel<<<(Cc * LL) / 256, 256>>>(x, w);
    reverb_mix_kernel<<<LL / 256, 256>>>(conv, out);
}

// round 3
// speedup vs baseline: 2.2787x; 1.0609x over previous
#include <cuda_runtime.h>
#include <cstdint>

#define Cc 64
#define CO 64
#define Ss 256
#define LL (Ss * Ss)

// 16 MB scratch for g[c,l] = x[c,l] * Wsum[c,l]
__device__ float g_scratch[Cc * LL];

// ---------------------------------------------------------------------------
// Kernel A: tap-gather, 4 pixels per thread, vectorized float4 loads.
// g[c,y,x] = x[c,y,x] * sum_{i,j valid} w[c*9 + i*3+j, (y+1-i)*S + (x+1-j)]
// For a 4-pixel group at aligned x0, kernel-row i needs (per plane j):
//   j=0: elements x0+1..x0+4 -> aligned f4 at x0 (elems 1..3) + scalar x0+4
//   j=1: elements x0..x0+3   -> aligned f4 at x0
//   j=2: elements x0-1..x0+2 -> scalar x0-1 + aligned f4 at x0 (elems 0..2)
// ---------------------------------------------------------------------------
__global__ __launch_bounds__(256) void reverb_gather_kernel(
    const float* __restrict__ x,   // (C, L)
    const float* __restrict__ w)   // (C*9, L)
{
    const int t = blockIdx.x * 256 + threadIdx.x;   // 0 .. C*L/4-1
    const int c = t >> 14;                          // LL/4 = 16384 groups/channel
    const int q = t & 16383;
    const int y  = q >> 6;
    const int x0 = (q & 63) << 2;

    const float* wc = w + (size_t)c * 9 * LL;

    const float mL = (x0 == 0)        ? 0.0f : 1.0f;   // left scalar valid?
    const float mR = (x0 == Ss - 4)   ? 0.0f : 1.0f;   // right scalar valid?
    const int xL = (x0 == 0) ? 0 : x0 - 1;
    const int xR = (x0 == Ss - 4) ? Ss - 1 : x0 + 4;

    float ws0 = 0.f, ws1 = 0.f, ws2 = 0.f, ws3 = 0.f;

#pragma unroll
    for (int i = 0; i < 3; i++) {
        const int ry = y + 1 - i;
        const bool vy = (unsigned)ry < (unsigned)Ss;
        const float my = vy ? 1.0f : 0.0f;
        const int ryc = vy ? ry : y;
        const int rowoff = ryc * Ss + x0;

        const float* p0 = wc + (size_t)(i * 3 + 0) * LL + rowoff;  // j=0 plane
        const float* p1 = wc + (size_t)(i * 3 + 1) * LL + rowoff;  // j=1 plane
        const float* p2 = wc + (size_t)(i * 3 + 2) * LL + rowoff;  // j=2 plane

        const float4 a = __ldg((const float4*)p0);
        const float  rsc = mR * __ldg(p0 - x0 + xR);     // plane j=0, scalar x0+4
        const float4 b = __ldg((const float4*)p1);
        const float  lsc = mL * __ldg(p2 - x0 + xL);     // plane j=2, scalar x0-1
        const float4 d = __ldg((const float4*)p2);

        ws0 = fmaf(my, (a.y + b.x) + lsc, ws0);
        ws1 = fmaf(my, (a.z + b.y) + d.x, ws1);
        ws2 = fmaf(my, (a.w + b.z) + d.y, ws2);
        ws3 = fmaf(my, (rsc + b.w) + d.z, ws3);
    }

    const float4 xv = __ldg((const float4*)(x + (size_t)t * 4));
    float4 gv;
    gv.x = xv.x * ws0;
    gv.y = xv.y * ws1;
    gv.z = xv.z * ws2;
    gv.w = xv.w * ws3;
    *((float4*)(g_scratch + (size_t)t * 4)) = gv;
}

// ---------------------------------------------------------------------------
// Kernel B: channel mix, register-tiled. out[o,l] = sum_c conv[c,o] * g[c,l]
// 256 threads/block = 64 pixel-lanes x 4 output-groups of 16.
// Each thread: 2 pixels (l, l+64) x 16 outputs = 16 f32x2 accumulator pairs
// packed along o, so conv pairs come straight from LDS.64.
// ---------------------------------------------------------------------------
__global__ __launch_bounds__(256) void reverb_mix_kernel(
    const float* __restrict__ conv,   // (C, CO)
    float* __restrict__ out)          // (CO, L)
{
    __shared__ float sconv[Cc * CO];  // 16 KB
    const int tid = threadIdx.x;
    for (int i = tid; i < Cc * CO; i += 256) sconv[i] = conv[i];
    __syncthreads();

    const int lane = tid & 63;
    const int og = tid >> 6;          // output group 0..3
    const int l0 = blockIdx.x * 128 + lane;   // pixel 0
    const int l1 = l0 + 64;                   // pixel 1

    unsigned long long acc0[8], acc1[8];      // 8 o-pairs x 2 pixels
#pragma unroll
    for (int op = 0; op < 8; op++) { acc0[op] = 0ull; acc1[op] = 0ull; }

#pragma unroll 4
    for (int c = 0; c < Cc; c++) {
        const float gv0 = g_scratch[c * LL + l0];
        const float gv1 = g_scratch[c * LL + l1];
        unsigned long long g0, g1;
        asm("mov.b64 %0, {%1, %1};" : "=l"(g0) : "f"(gv0));
        asm("mov.b64 %0, {%1, %1};" : "=l"(g1) : "f"(gv1));
        const unsigned long long* cv =
            reinterpret_cast<const unsigned long long*>(sconv + c * CO + og * 16);
#pragma unroll
        for (int op = 0; op < 8; op++) {
            const unsigned long long cp = cv[op];
            asm("fma.rn.f32x2 %0, %1, %2, %0;" : "+l"(acc0[op]) : "l"(cp), "l"(g0));
            asm("fma.rn.f32x2 %0, %1, %2, %0;" : "+l"(acc1[op]) : "l"(cp), "l"(g1));
        }
    }

#pragma unroll
    for (int op = 0; op < 8; op++) {
        const int o = og * 16 + 2 * op;
        unsigned int lo, hi;
        asm("mov.b64 {%0, %1}, %2;" : "=r"(lo), "=r"(hi) : "l"(acc0[op]));
        out[(size_t)o * LL + l0] = __uint_as_float(lo);
        out[(size_t)(o + 1) * LL + l0] = __uint_as_float(hi);
        asm("mov.b64 {%0, %1}, %2;" : "=r"(lo), "=r"(hi) : "l"(acc1[op]));
        out[(size_t)o * LL + l1] = __uint_as_float(lo);
        out[(size_t)(o + 1) * LL + l1] = __uint_as_float(hi);
    }
}

extern "C" void kernel_launch(void* const* d_in, const int* in_sizes, int n_in,
                              void* d_out, int out_size) {
    const float* x    = (const float*)d_in[0];  // (1, C, S, S)
    const float* w    = (const float*)d_in[1];  // (1, C*9, L)
    const float* conv = (const float*)d_in[2];  // (C, CO)
    float* out = (float*)d_out;                 // (1, CO, S, S)

    reverb_gather_kernel<<<(Cc * LL / 4) / 256, 256>>>(x, w);
    reverb_mix_kernel<<<LL / 128, 256>>>(conv, out);
}

// round 4
// speedup vs baseline: 2.3755x; 1.0425x over previous
#include <cuda_runtime.h>
#include <cstdint>

#define Cc 64
#define CO 64
#define Ss 256
#define LL (Ss * Ss)

// 16 MB scratch for g[c,l] = x[c,l] * Wsum[c,l]
__device__ float g_scratch[Cc * LL];

// ---------------------------------------------------------------------------
// Kernel A: tap-gather, 4 pixels per thread, vectorized float4 loads.
// g[c,y,x] = x[c,y,x] * sum_{i,j valid} w[c*9 + i*3+j, (y+1-i)*S + (x+1-j)]
// ---------------------------------------------------------------------------
__global__ __launch_bounds__(256) void reverb_gather_kernel(
    const float* __restrict__ x,   // (C, L)
    const float* __restrict__ w)   // (C*9, L)
{
    const int t = blockIdx.x * 256 + threadIdx.x;   // 0 .. C*L/4-1
    const int c = t >> 14;                          // LL/4 = 16384 groups/channel
    const int q = t & 16383;
    const int y  = q >> 6;
    const int x0 = (q & 63) << 2;

    const float* wc = w + (size_t)c * 9 * LL;

    const float mL = (x0 == 0)        ? 0.0f : 1.0f;
    const float mR = (x0 == Ss - 4)   ? 0.0f : 1.0f;
    const int xL = (x0 == 0) ? 0 : x0 - 1;
    const int xR = (x0 == Ss - 4) ? Ss - 1 : x0 + 4;

    float ws0 = 0.f, ws1 = 0.f, ws2 = 0.f, ws3 = 0.f;

#pragma unroll
    for (int i = 0; i < 3; i++) {
        const int ry = y + 1 - i;
        const bool vy = (unsigned)ry < (unsigned)Ss;
        const float my = vy ? 1.0f : 0.0f;
        const int ryc = vy ? ry : y;
        const int rowoff = ryc * Ss + x0;

        const float* p0 = wc + (size_t)(i * 3 + 0) * LL + rowoff;
        const float* p1 = wc + (size_t)(i * 3 + 1) * LL + rowoff;
        const float* p2 = wc + (size_t)(i * 3 + 2) * LL + rowoff;

        const float4 a = __ldg((const float4*)p0);
        const float  rsc = mR * __ldg(p0 - x0 + xR);
        const float4 b = __ldg((const float4*)p1);
        const float  lsc = mL * __ldg(p2 - x0 + xL);
        const float4 d = __ldg((const float4*)p2);

        ws0 = fmaf(my, (a.y + b.x) + lsc, ws0);
        ws1 = fmaf(my, (a.z + b.y) + d.x, ws1);
        ws2 = fmaf(my, (a.w + b.z) + d.y, ws2);
        ws3 = fmaf(my, (rsc + b.w) + d.z, ws3);
    }

    const float4 xv = __ldg((const float4*)(x + (size_t)t * 4));
    float4 gv;
    gv.x = xv.x * ws0;
    gv.y = xv.y * ws1;
    gv.z = xv.z * ws2;
    gv.w = xv.w * ws3;
    *((float4*)(g_scratch + (size_t)t * 4)) = gv;
}

// ---------------------------------------------------------------------------
// Kernel B: channel mix. out[o,l] = sum_c conv[c,o] * g[c,l]
// Block: 256 threads = 8 warps; warp w owns outputs [8w, 8w+8).
// Lane owns 4 consecutive pixels (one LDG.128 per c); same g line reused by
// all 8 warps via L1. Accumulators: 4 px x 4 o-pairs (f32x2), o-packed so
// conv pairs come from LDS.128 directly. Epilogue: 8 coalesced STG.128.
// ---------------------------------------------------------------------------
__global__ __launch_bounds__(256, 3) void reverb_mix_kernel(
    const float* __restrict__ conv,   // (C, CO)
    float* __restrict__ out)          // (CO, L)
{
    __shared__ float sconv[Cc * CO];  // 16 KB
    const int tid = threadIdx.x;
    for (int i = tid; i < Cc * CO; i += 256) sconv[i] = conv[i];
    __syncthreads();

    const int og   = tid >> 5;                       // warp id = output group 0..7
    const int lane = tid & 31;
    const int l0 = blockIdx.x * 128 + lane * 4;      // 4 consecutive pixels

    unsigned long long acc[4][4];   // [pixel][o-pair]
#pragma unroll
    for (int p = 0; p < 4; p++)
#pragma unroll
        for (int op = 0; op < 4; op++) acc[p][op] = 0ull;

#pragma unroll 4
    for (int c = 0; c < Cc; c++) {
        const float4 g4 = *(const float4*)(g_scratch + (size_t)c * LL + l0);
        unsigned long long gp[4];
        asm("mov.b64 %0, {%1, %1};" : "=l"(gp[0]) : "f"(g4.x));
        asm("mov.b64 %0, {%1, %1};" : "=l"(gp[1]) : "f"(g4.y));
        asm("mov.b64 %0, {%1, %1};" : "=l"(gp[2]) : "f"(g4.z));
        asm("mov.b64 %0, {%1, %1};" : "=l"(gp[3]) : "f"(g4.w));

        // 8 conv values = 2 x LDS.128 (broadcast within warp)
        const float4* cvbase = (const float4*)(sconv + c * CO + og * 8);
        const float4 cva = cvbase[0];
        const float4 cvb = cvbase[1];
        unsigned long long cp[4];
        asm("mov.b64 %0, {%1, %2};" : "=l"(cp[0]) : "f"(cva.x), "f"(cva.y));
        asm("mov.b64 %0, {%1, %2};" : "=l"(cp[1]) : "f"(cva.z), "f"(cva.w));
        asm("mov.b64 %0, {%1, %2};" : "=l"(cp[2]) : "f"(cvb.x), "f"(cvb.y));
        asm("mov.b64 %0, {%1, %2};" : "=l"(cp[3]) : "f"(cvb.z), "f"(cvb.w));

#pragma unroll
        for (int op = 0; op < 4; op++) {
#pragma unroll
            for (int p = 0; p < 4; p++) {
                asm("fma.rn.f32x2 %0, %1, %2, %0;"
                    : "+l"(acc[p][op]) : "l"(cp[op]), "l"(gp[p]));
            }
        }
    }

    // Epilogue: unpack and store one float4 (4 pixels) per output row
#pragma unroll
    for (int op = 0; op < 4; op++) {
        unsigned int lo[4], hi[4];
#pragma unroll
        for (int p = 0; p < 4; p++) {
            asm("mov.b64 {%0, %1}, %2;" : "=r"(lo[p]), "=r"(hi[p]) : "l"(acc[p][op]));
        }
        const int o = og * 8 + 2 * op;
        float4 v0, v1;
        v0.x = __uint_as_float(lo[0]); v0.y = __uint_as_float(lo[1]);
        v0.z = __uint_as_float(lo[2]); v0.w = __uint_as_float(lo[3]);
        v1.x = __uint_as_float(hi[0]); v1.y = __uint_as_float(hi[1]);
        v1.z = __uint_as_float(hi[2]); v1.w = __uint_as_float(hi[3]);
        *(float4*)(out + (size_t)o * LL + l0) = v0;
        *(float4*)(out + (size_t)(o + 1) * LL + l0) = v1;
    }
}

extern "C" void kernel_launch(void* const* d_in, const int* in_sizes, int n_in,
                              void* d_out, int out_size) {
    const float* x    = (const float*)d_in[0];  // (1, C, S, S)
    const float* w    = (const float*)d_in[1];  // (1, C*9, L)
    const float* conv = (const float*)d_in[2];  // (C, CO)
    float* out = (float*)d_out;                 // (1, CO, S, S)

    reverb_gather_kernel<<<(Cc * LL / 4) / 256, 256>>>(x, w);
    reverb_mix_kernel<<<LL / 128, 256>>>(conv, out);
}